// round 14
// baseline (speedup 1.0000x reference)
#include <cuda_runtime.h>
#include <cuda_fp16.h>

#define NTHREADS 512
#define GRIDX 304          // 2 CTAs x 152 SMs, persistent
#define UH 80              // halves per u row
#define XSTR 68            // floats per x row
#define PFS 80             // halves per facet block in partial buffer
#define PWS 648            // halves per warp block

// smem floats: us 320 (=[8][80] halves) | xs 544 | part 16*648/2 = 5184
#define SMEM_FLOATS (320 + 544 + 16 * PWS / 2)

// Reduce-scatter 8 values over lane bits 1-3: lane (b1,b2,b3) ends with the
// 8-lane-group sum of v[b1 + 2*b2 + 4*b3].
__device__ __forceinline__ float reduce_scatter8(const float* v, int lane) {
    float a[4];
    {
        const bool hb = (lane & 8) != 0;
        #pragma unroll
        for (int k = 0; k < 4; k++) {
            float snd = hb ? v[k] : v[k + 4];
            float rcv = __shfl_xor_sync(0xffffffffu, snd, 8);
            a[k] = (hb ? v[k + 4] : v[k]) + rcv;
        }
    }
    float c[2];
    {
        const bool hb = (lane & 4) != 0;
        #pragma unroll
        for (int k = 0; k < 2; k++) {
            float snd = hb ? a[k] : a[k + 2];
            float rcv = __shfl_xor_sync(0xffffffffu, snd, 4);
            c[k] = (hb ? a[k + 2] : a[k]) + rcv;
        }
    }
    {
        const bool hb = (lane & 2) != 0;
        float snd = hb ? c[0] : c[1];
        float rcv = __shfl_xor_sync(0xffffffffu, snd, 2);
        return (hb ? c[1] : c[0]) + rcv;
    }
}

__global__ __launch_bounds__(NTHREADS, 2)
void hete_attention_kernel(const float* __restrict__ feat,
                           const float* __restrict__ meta,
                           float* __restrict__ out,
                           int Btot)
{
    extern __shared__ float smem[];
    __half* us   = (__half*)smem;              // [8][80] halves = 320 floats
    float*  xs   = smem + 320;                 // [8][68]
    __half* part = (__half*)(smem + 320 + 544);// [16 w][8 f][80]

    const int t    = threadIdx.x;
    const int lane = t & 31;
    const int w    = t >> 5;
    const int hi   = lane >> 4;                // f parity (bit4)
    const int po   = lane & 1;                 // pair parity (bit0)
    const int a    = (lane >> 1) & 7;          // 8-d chunk index

    // ownership (round-8 verified): rows k=0..7:
    // n = 4w + (k>>1), f = 4*(k&1) + 2*po + hi, d = 8a..8a+7
    const int fA = 2 * po + hi;
    const int fB = fA + 4;
    const __half* uA = us + fA * UH + a * 8;
    const __half* uB = us + fB * UH + a * 8;
    __half* pA = part + w * PWS + fA * PFS + a * 8;
    __half* pB = part + w * PWS + fB * PFS + a * 8;
    const int gidx = lane & 17;

    int bi = blockIdx.x;
    __half2 zr[32];

    // ---- prologue: demand-load z(bi) raw ----
    if (bi < Btot) {
        const float4* gz = (const float4*)(meta + (size_t)bi * 32768) + w * 512 + lane;
        #pragma unroll
        for (int i = 0; i < 16; i++) {
            float4 v = gz[i * 32];
            zr[2 * i]     = __floats2half2_rn(v.x, v.y);
            zr[2 * i + 1] = __floats2half2_rn(v.z, v.w);
        }
    }

    for (; bi < Btot; bi += GRIDX) {
        const int  bn = bi + GRIDX;
        const bool hn = bn < Btot;
        const float* nb = hn ? (meta + (size_t)bn * 32768 + t * 32) : nullptr;

        // ---- x: load + L2-normalize per facet (warps 0..7); u0 = x_norm ----
        if (w < 8) {
            float2 v = *(const float2*)(feat + (size_t)bi * 512 + w * 64 + lane * 2);
            float s = v.x * v.x + v.y * v.y;
            #pragma unroll
            for (int o = 16; o; o >>= 1) s += __shfl_xor_sync(0xffffffffu, s, o);
            float r = rsqrtf(fmaxf(s, 1e-24f));
            float2 nv = make_float2(v.x * r, v.y * r);
            *(float2*)(xs + w * XSTR + lane * 2) = nv;
            *(__half2*)(us + w * UH + lane * 2) = __floats2half2_rn(nv.x, nv.y);
        }

        // ---- L2 prefetch of next batch, first half + x lines ----
        if (hn) {
            asm volatile("prefetch.global.L2 [%0];" :: "l"(nb));
            if (t < 16) {
                const float* nf = feat + (size_t)bn * 512 + t * 32;
                asm volatile("prefetch.global.L2 [%0];" :: "l"(nf));
            }
        }

        // ---- one-time lane-pair transpose: thread ends owning 8 rows x 8 d ----
        #pragma unroll
        for (int k = 0; k < 8; k++) {
            unsigned a0 = *(unsigned*)&zr[4 * k];
            unsigned a1 = *(unsigned*)&zr[4 * k + 1];
            unsigned b0 = *(unsigned*)&zr[4 * k + 2];
            unsigned b1 = *(unsigned*)&zr[4 * k + 3];
            unsigned s0 = po ? a0 : b0;
            unsigned s1 = po ? a1 : b1;
            unsigned r0 = __shfl_xor_sync(0xffffffffu, s0, 1);
            unsigned r1 = __shfl_xor_sync(0xffffffffu, s1, 1);
            unsigned o0 = po ? r0 : a0, o1 = po ? r1 : a1;
            unsigned o2 = po ? b0 : r0, o3 = po ? b1 : r1;
            zr[4 * k]     = *(__half2*)&o0;
            zr[4 * k + 1] = *(__half2*)&o1;
            zr[4 * k + 2] = *(__half2*)&o2;
            zr[4 * k + 3] = *(__half2*)&o3;
        }

        // ---- row reciprocal norms ----
        float rzv;
        {
            float sd[8];
            #pragma unroll
            for (int k = 0; k < 8; k++) {
                __half2 h = __hmul2(zr[4 * k], zr[4 * k]);
                h = __hfma2(zr[4 * k + 1], zr[4 * k + 1], h);
                h = __hfma2(zr[4 * k + 2], zr[4 * k + 2], h);
                h = __hfma2(zr[4 * k + 3], zr[4 * k + 3], h);
                float2 fx = __half22float2(h);
                sd[k] = fx.x + fx.y;
            }
            float S = reduce_scatter8(sd, lane);
            rzv = rsqrtf(fmaxf(S, 1e-24f));
        }

        __syncthreads();       // top barrier: us/xs ready; part safe to rewrite

        #pragma unroll
        for (int it = 0; it < 3; it++) {
            // ---- u chunks for the 2 facets (LDS.128, conflict-free) ----
            __half2 uhA[4], uhB[4];
            *(uint4*)uhA = *(const uint4*)uA;
            *(uint4*)uhB = *(const uint4*)uB;

            // ---- 8 row-dots over own 8 d ----
            float dj[8];
            #pragma unroll
            for (int k = 0; k < 8; k++) {
                const __half2* uu = (k & 1) ? uhB : uhA;
                __half2 h = __hmul2(zr[4 * k], uu[0]);
                h = __hfma2(zr[4 * k + 1], uu[1], h);
                h = __hfma2(zr[4 * k + 2], uu[2], h);
                h = __hfma2(zr[4 * k + 3], uu[3], h);
                float2 fx = __half22float2(h);
                dj[k] = fx.x + fx.y;
            }

            // ---- scatter-reduce -> logit; softmax over f ----
            float L = reduce_scatter8(dj, lane) * rzv;
            float e = __expf(L);                    // cosines in [-1,1]
            float s = e;
            s += __shfl_xor_sync(0xffffffffu, s, 1);
            s += __shfl_xor_sync(0xffffffffu, s, 2);
            s += __shfl_xor_sync(0xffffffffu, s, 16);
            float p_eff = __fdividef(e, s) * rzv;

            // ---- packed fp16 gather of own 8 rows' p ----
            __half ph = __float2half(p_eff);
            unsigned pv = (unsigned)__half_as_ushort(ph);
            unsigned p8 = __shfl_xor_sync(0xffffffffu, pv, 8);
            __half2 P2 = __halves2half2(ph, __ushort_as_half((unsigned short)p8));
            unsigned P2u = *(unsigned*)&P2;
            __half2 g[4];
            #pragma unroll
            for (int k = 0; k < 4; k++) {
                unsigned gu = __shfl_sync(0xffffffffu, P2u, gidx | (k << 1));
                g[k] = *(__half2*)&gu;
            }

            // ---- pass 2: fp16 accumulate ----
            __half2 accA[4], accB[4];
            {
                __half2 ph0 = __low2half2(g[0]);
                __half2 ph1 = __low2half2(g[1]);
                #pragma unroll
                for (int r = 0; r < 4; r++) {
                    accA[r] = __hmul2(zr[r], ph0);
                    accB[r] = __hmul2(zr[4 + r], ph1);
                }
                #pragma unroll
                for (int k = 2; k < 8; k++) {
                    __half2 pk = (k < 4) ? __low2half2(g[k]) : __high2half2(g[k - 4]);
                    __half2* acc = (k & 1) ? accB : accA;
                    #pragma unroll
                    for (int r = 0; r < 4; r++)
                        acc[r] = __hfma2(zr[4 * k + r], pk, acc[r]);
                }
            }
            *(uint4*)pA = *(uint4*)accA;
            *(uint4*)pB = *(uint4*)accB;

            // ---- it=2: zr is dead — demand-load NEXT batch's z (L2 hits) ----
            if (it == 2 && hn) {
                const float4* gz = (const float4*)(meta + (size_t)bn * 32768)
                                 + w * 512 + lane;
                #pragma unroll
                for (int i = 0; i < 16; i++) {
                    float4 v = gz[i * 32];
                    zr[2 * i]     = __floats2half2_rn(v.x, v.y);
                    zr[2 * i + 1] = __floats2half2_rn(v.z, v.w);
                }
            }
            __syncthreads();                        // partials visible

            // ---- prefetch second half after it=0 ----
            if (it == 0 && hn)
                asm volatile("prefetch.global.L2 [%0];" :: "l"(nb + 512 * 32));

            // ---- epilogue: warp f<8 combines 16 partials (fp32), +x ----
            if (w < 8) {
                int d0 = lane * 2;
                float2 v = *(const float2*)(xs + w * XSTR + d0);
                #pragma unroll
                for (int gg = 0; gg < 16; gg++) {
                    __half2 hv = *(const __half2*)(part + gg * PWS + w * PFS + d0);
                    float2 fv = __half22float2(hv);
                    v.x += fv.x; v.y += fv.y;
                }
                if (it < 2) {
                    float s2 = v.x * v.x + v.y * v.y;
                    #pragma unroll
                    for (int o = 16; o; o >>= 1) s2 += __shfl_xor_sync(0xffffffffu, s2, o);
                    float r = rsqrtf(fmaxf(s2, 1e-24f));
                    *(__half2*)(us + w * UH + d0) = __floats2half2_rn(v.x * r, v.y * r);
                } else {
                    *(float2*)(out + (size_t)bi * 512 + w * 64 + d0) = v;
                }
            }
            if (it < 2) __syncthreads();   // us ready (it=2: top barrier covers)
        }
    }
}

extern "C" void kernel_launch(void* const* d_in, const int* in_sizes, int n_in,
                              void* d_out, int out_size)
{
    const float* feat = (const float*)d_in[0];   // [B, 512]
    const float* meta = (const float*)d_in[1];   // [B, 64, 512]
    float* out = (float*)d_out;

    const int B = in_sizes[0] / 512;             // 2048
    const size_t smem_bytes = (size_t)SMEM_FLOATS * sizeof(float);

    cudaFuncSetAttribute(hete_attention_kernel,
                         cudaFuncAttributeMaxDynamicSharedMemorySize,
                         (int)smem_bytes);

    hete_attention_kernel<<<GRIDX, NTHREADS, smem_bytes>>>(feat, meta, out, B);
}

// round 15
// speedup vs baseline: 1.0759x; 1.0759x over previous
#include <cuda_runtime.h>
#include <cuda_fp16.h>

#define NTHREADS 512
#define GRIDX 304          // 2 CTAs x 152 SMs, persistent
#define UH 80              // halves per u row
#define XSTR 68            // floats per x row
#define PFS 80             // halves per facet block in partial buffer
#define PWS 648            // halves per warp block

// smem floats: us 320 (=[8][80] halves) | xs 544 | part 16*648/2 = 5184
#define SMEM_FLOATS (320 + 544 + 16 * PWS / 2)

// Reduce-scatter 8 values over lane bits 1-3: lane (b1,b2,b3) ends with the
// 8-lane-group sum of v[b1 + 2*b2 + 4*b3].
__device__ __forceinline__ float reduce_scatter8(const float* v, int lane) {
    float a[4];
    {
        const bool hb = (lane & 8) != 0;
        #pragma unroll
        for (int k = 0; k < 4; k++) {
            float snd = hb ? v[k] : v[k + 4];
            float rcv = __shfl_xor_sync(0xffffffffu, snd, 8);
            a[k] = (hb ? v[k + 4] : v[k]) + rcv;
        }
    }
    float c[2];
    {
        const bool hb = (lane & 4) != 0;
        #pragma unroll
        for (int k = 0; k < 2; k++) {
            float snd = hb ? a[k] : a[k + 2];
            float rcv = __shfl_xor_sync(0xffffffffu, snd, 4);
            c[k] = (hb ? a[k + 2] : a[k]) + rcv;
        }
    }
    {
        const bool hb = (lane & 2) != 0;
        float snd = hb ? c[0] : c[1];
        float rcv = __shfl_xor_sync(0xffffffffu, snd, 2);
        return (hb ? c[1] : c[0]) + rcv;
    }
}

__global__ __launch_bounds__(NTHREADS, 2)
void hete_attention_kernel(const float* __restrict__ feat,
                           const float* __restrict__ meta,
                           float* __restrict__ out,
                           int Btot)
{
    extern __shared__ float smem[];
    __half* us   = (__half*)smem;              // [8][80] halves = 320 floats
    float*  xs   = smem + 320;                 // [8][68]
    __half* part = (__half*)(smem + 320 + 544);// [16 w][8 f][80]

    const int t    = threadIdx.x;
    const int lane = t & 31;
    const int w    = t >> 5;
    const int hi   = lane >> 4;                // f parity (bit4)
    const int po   = lane & 1;                 // pair parity (bit0)
    const int a    = (lane >> 1) & 7;          // 8-d chunk index

    // ownership (round-8 verified): rows k=0..7:
    // n = 4w + (k>>1), f = 4*(k&1) + 2*po + hi, d = 8a..8a+7
    const int fA = 2 * po + hi;
    const int fB = fA + 4;
    const __half* uA = us + fA * UH + a * 8;
    const __half* uB = us + fB * UH + a * 8;
    __half* pA = part + w * PWS + fA * PFS + a * 8;
    __half* pB = part + w * PWS + fB * PFS + a * 8;
    const int gidx = lane & 17;

    for (int bi = blockIdx.x; bi < Btot; bi += GRIDX) {
        // ---- x: load + L2-normalize per facet (warps 0..7); u0 = x_norm ----
        if (w < 8) {
            float2 v = *(const float2*)(feat + (size_t)bi * 512 + w * 64 + lane * 2);
            float s = v.x * v.x + v.y * v.y;
            #pragma unroll
            for (int o = 16; o; o >>= 1) s += __shfl_xor_sync(0xffffffffu, s, o);
            float r = rsqrtf(fmaxf(s, 1e-24f));
            float2 nv = make_float2(v.x * r, v.y * r);
            *(float2*)(xs + w * XSTR + lane * 2) = nv;
            *(__half2*)(us + w * UH + lane * 2) = __floats2half2_rn(nv.x, nv.y);
        }

        // ---- z: fully coalesced HBM -> fp16 registers ----
        __half2 zr[32];
        {
            const float4* gz = (const float4*)(meta + (size_t)bi * 32768) + w * 512 + lane;
            #pragma unroll
            for (int i = 0; i < 16; i++) {
                float4 v = gz[i * 32];
                zr[2 * i]     = __floats2half2_rn(v.x, v.y);
                zr[2 * i + 1] = __floats2half2_rn(v.z, v.w);
            }
        }

        // ---- fire-and-forget L2 prefetch of NEXT batch (z: 1024 lines, x: 16) ----
        {
            int bn = bi + GRIDX;
            if (bn < Btot) {
                const float* nb = meta + (size_t)bn * 32768 + t * 32;
                asm volatile("prefetch.global.L2 [%0];" :: "l"(nb));
                asm volatile("prefetch.global.L2 [%0];" :: "l"(nb + 512 * 32));
                if (t < 16) {
                    const float* nf = feat + (size_t)bn * 512 + t * 32;
                    asm volatile("prefetch.global.L2 [%0];" :: "l"(nf));
                }
            }
        }

        // ---- one-time lane-pair transpose: thread ends owning 8 rows x 8 d ----
        #pragma unroll
        for (int k = 0; k < 8; k++) {
            unsigned a0 = *(unsigned*)&zr[4 * k];
            unsigned a1 = *(unsigned*)&zr[4 * k + 1];
            unsigned b0 = *(unsigned*)&zr[4 * k + 2];
            unsigned b1 = *(unsigned*)&zr[4 * k + 3];
            unsigned s0 = po ? a0 : b0;
            unsigned s1 = po ? a1 : b1;
            unsigned r0 = __shfl_xor_sync(0xffffffffu, s0, 1);
            unsigned r1 = __shfl_xor_sync(0xffffffffu, s1, 1);
            unsigned o0 = po ? r0 : a0, o1 = po ? r1 : a1;
            unsigned o2 = po ? b0 : r0, o3 = po ? b1 : r1;
            zr[4 * k]     = *(__half2*)&o0;
            zr[4 * k + 1] = *(__half2*)&o1;
            zr[4 * k + 2] = *(__half2*)&o2;
            zr[4 * k + 3] = *(__half2*)&o3;
        }

        // ---- row reciprocal norms ----
        float rzv;
        {
            float sd[8];
            #pragma unroll
            for (int k = 0; k < 8; k++) {
                __half2 h = __hmul2(zr[4 * k], zr[4 * k]);
                h = __hfma2(zr[4 * k + 1], zr[4 * k + 1], h);
                h = __hfma2(zr[4 * k + 2], zr[4 * k + 2], h);
                h = __hfma2(zr[4 * k + 3], zr[4 * k + 3], h);
                float2 fx = __half22float2(h);
                sd[k] = fx.x + fx.y;
            }
            float S = reduce_scatter8(sd, lane);
            rzv = rsqrtf(fmaxf(S, 1e-24f));
        }

        __syncthreads();       // top barrier: us/xs ready; part safe to rewrite

        #pragma unroll
        for (int it = 0; it < 3; it++) {
            // ---- u chunks for the 2 facets (LDS.128, conflict-free) ----
            __half2 uhA[4], uhB[4];
            *(uint4*)uhA = *(const uint4*)uA;
            *(uint4*)uhB = *(const uint4*)uB;

            // ---- 8 row-dots over own 8 d ----
            float dj[8];
            #pragma unroll
            for (int k = 0; k < 8; k++) {
                const __half2* uu = (k & 1) ? uhB : uhA;
                __half2 h = __hmul2(zr[4 * k], uu[0]);
                h = __hfma2(zr[4 * k + 1], uu[1], h);
                h = __hfma2(zr[4 * k + 2], uu[2], h);
                h = __hfma2(zr[4 * k + 3], uu[3], h);
                float2 fx = __half22float2(h);
                dj[k] = fx.x + fx.y;
            }

            // ---- scatter-reduce -> logit; softmax over f ----
            float L = reduce_scatter8(dj, lane) * rzv;
            float e = __expf(L);                    // cosines in [-1,1]
            float s = e;
            s += __shfl_xor_sync(0xffffffffu, s, 1);
            s += __shfl_xor_sync(0xffffffffu, s, 2);
            s += __shfl_xor_sync(0xffffffffu, s, 16);
            float p_eff = __fdividef(e, s) * rzv;

            // ---- packed fp16 gather of own 8 rows' p ----
            __half ph = __float2half(p_eff);
            unsigned pv = (unsigned)__half_as_ushort(ph);
            unsigned p8 = __shfl_xor_sync(0xffffffffu, pv, 8);
            __half2 P2 = __halves2half2(ph, __ushort_as_half((unsigned short)p8));
            unsigned P2u = *(unsigned*)&P2;
            __half2 g[4];
            #pragma unroll
            for (int k = 0; k < 4; k++) {
                unsigned gu = __shfl_sync(0xffffffffu, P2u, gidx | (k << 1));
                g[k] = *(__half2*)&gu;
            }

            // ---- pass 2: fp16 accumulate ----
            __half2 accA[4], accB[4];
            {
                __half2 ph0 = __low2half2(g[0]);
                __half2 ph1 = __low2half2(g[1]);
                #pragma unroll
                for (int r = 0; r < 4; r++) {
                    accA[r] = __hmul2(zr[r], ph0);
                    accB[r] = __hmul2(zr[4 + r], ph1);
                }
                #pragma unroll
                for (int k = 2; k < 8; k++) {
                    __half2 pk = (k < 4) ? __low2half2(g[k]) : __high2half2(g[k - 4]);
                    __half2* acc = (k & 1) ? accB : accA;
                    #pragma unroll
                    for (int r = 0; r < 4; r++)
                        acc[r] = __hfma2(zr[4 * k + r], pk, acc[r]);
                }
            }
            *(uint4*)pA = *(uint4*)accA;
            *(uint4*)pB = *(uint4*)accB;
            __syncthreads();                        // partials visible

            // ---- epilogue: warp f<8 combines 16 partials (fp32), +x ----
            if (w < 8) {
                int d0 = lane * 2;
                float2 v = *(const float2*)(xs + w * XSTR + d0);
                #pragma unroll
                for (int gg = 0; gg < 16; gg++) {
                    __half2 hv = *(const __half2*)(part + gg * PWS + w * PFS + d0);
                    float2 fv = __half22float2(hv);
                    v.x += fv.x; v.y += fv.y;
                }
                if (it < 2) {
                    float s2 = v.x * v.x + v.y * v.y;
                    #pragma unroll
                    for (int o = 16; o; o >>= 1) s2 += __shfl_xor_sync(0xffffffffu, s2, o);
                    float r = rsqrtf(fmaxf(s2, 1e-24f));
                    *(__half2*)(us + w * UH + d0) = __floats2half2_rn(v.x * r, v.y * r);
                } else {
                    *(float2*)(out + (size_t)bi * 512 + w * 64 + d0) = v;
                }
            }
            // it<2: barrier so next iter's dots see the new u.
            // it==2: NO barrier needed — next batch's top barrier (after x-norm,
            // z load, transpose, norms) orders all subsequent smem writes; xs/us
            // rewrites before it are warp-private rows (same-warp program order).
            if (it < 2) __syncthreads();
        }
    }
}

extern "C" void kernel_launch(void* const* d_in, const int* in_sizes, int n_in,
                              void* d_out, int out_size)
{
    const float* feat = (const float*)d_in[0];   // [B, 512]
    const float* meta = (const float*)d_in[1];   // [B, 64, 512]
    float* out = (float*)d_out;

    const int B = in_sizes[0] / 512;             // 2048
    const size_t smem_bytes = (size_t)SMEM_FLOATS * sizeof(float);

    cudaFuncSetAttribute(hete_attention_kernel,
                         cudaFuncAttributeMaxDynamicSharedMemorySize,
                         (int)smem_bytes);

    hete_attention_kernel<<<GRIDX, NTHREADS, smem_bytes>>>(feat, meta, out, B);
}

// round 16
// speedup vs baseline: 1.1815x; 1.0982x over previous
#include <cuda_runtime.h>
#include <cuda_fp16.h>

#define NTHREADS 512
#define GRIDX 304          // 2 CTAs x 152 SMs, persistent
#define UH 80              // halves per u row
#define XSTR 68            // floats per x row
#define PFS 80             // halves per facet block in partial buffer
#define PWS 648            // halves per warp block

// smem floats: us 320 (=[8][80] halves) | xs 544 | part 16*648/2 = 5184
#define SMEM_FLOATS (320 + 544 + 16 * PWS / 2)

// Reduce-scatter 8 values over lane bits 1-3: lane (b1,b2,b3) ends with the
// 8-lane-group sum of v[b1 + 2*b2 + 4*b3].
__device__ __forceinline__ float reduce_scatter8(const float* v, int lane) {
    float a[4];
    {
        const bool hb = (lane & 8) != 0;
        #pragma unroll
        for (int k = 0; k < 4; k++) {
            float snd = hb ? v[k] : v[k + 4];
            float rcv = __shfl_xor_sync(0xffffffffu, snd, 8);
            a[k] = (hb ? v[k + 4] : v[k]) + rcv;
        }
    }
    float c[2];
    {
        const bool hb = (lane & 4) != 0;
        #pragma unroll
        for (int k = 0; k < 2; k++) {
            float snd = hb ? a[k] : a[k + 2];
            float rcv = __shfl_xor_sync(0xffffffffu, snd, 4);
            c[k] = (hb ? a[k + 2] : a[k]) + rcv;
        }
    }
    {
        const bool hb = (lane & 2) != 0;
        float snd = hb ? c[0] : c[1];
        float rcv = __shfl_xor_sync(0xffffffffu, snd, 2);
        return (hb ? c[1] : c[0]) + rcv;
    }
}

__global__ __launch_bounds__(NTHREADS, 2)
void hete_attention_kernel(const float* __restrict__ feat,
                           const float* __restrict__ meta,
                           float* __restrict__ out,
                           int Btot)
{
    extern __shared__ float smem[];
    __half* us   = (__half*)smem;              // [8][80] halves = 320 floats
    float*  xs   = smem + 320;                 // [8][68]
    __half* part = (__half*)(smem + 320 + 544);// [16 w][8 f][80]

    const int t    = threadIdx.x;
    const int lane = t & 31;
    const int w    = t >> 5;
    const int hi   = lane >> 4;                // f parity (bit4)
    const int po   = lane & 1;                 // pair parity (bit0)
    const int a    = (lane >> 1) & 7;          // 8-d chunk index

    // ownership (round-8 verified): rows k=0..7:
    // n = 4w + (k>>1), f = 4*(k&1) + 2*po + hi, d = 8a..8a+7
    const int fA = 2 * po + hi;
    const int fB = fA + 4;
    const __half* uA = us + fA * UH + a * 8;
    const __half* uB = us + fB * UH + a * 8;
    __half* pA = part + w * PWS + fA * PFS + a * 8;
    __half* pB = part + w * PWS + fB * PFS + a * 8;
    const int gidx = lane & 17;

    for (int bi = blockIdx.x; bi < Btot; bi += GRIDX) {
        // ---- x: load + L2-normalize per facet (warps 0..7); u0 = x_norm ----
        if (w < 8) {
            float2 v = *(const float2*)(feat + (size_t)bi * 512 + w * 64 + lane * 2);
            float s = v.x * v.x + v.y * v.y;
            #pragma unroll
            for (int o = 16; o; o >>= 1) s += __shfl_xor_sync(0xffffffffu, s, o);
            float r = rsqrtf(fmaxf(s, 1e-24f));
            float2 nv = make_float2(v.x * r, v.y * r);
            *(float2*)(xs + w * XSTR + lane * 2) = nv;
            *(__half2*)(us + w * UH + lane * 2) = __floats2half2_rn(nv.x, nv.y);
        }

        // ---- z: fully coalesced HBM -> fp16 registers (streaming: read-once) ----
        __half2 zr[32];
        {
            const float4* gz = (const float4*)(meta + (size_t)bi * 32768) + w * 512 + lane;
            #pragma unroll
            for (int i = 0; i < 16; i++) {
                float4 v = __ldcs(gz + i * 32);
                zr[2 * i]     = __floats2half2_rn(v.x, v.y);
                zr[2 * i + 1] = __floats2half2_rn(v.z, v.w);
            }
        }

        // ---- fire-and-forget L2 prefetch of NEXT batch (z: 1024 lines, x: 16) ----
        {
            int bn = bi + GRIDX;
            if (bn < Btot) {
                const float* nb = meta + (size_t)bn * 32768 + t * 32;
                asm volatile("prefetch.global.L2 [%0];" :: "l"(nb));
                asm volatile("prefetch.global.L2 [%0];" :: "l"(nb + 512 * 32));
                if (t < 16) {
                    const float* nf = feat + (size_t)bn * 512 + t * 32;
                    asm volatile("prefetch.global.L2 [%0];" :: "l"(nf));
                }
            }
        }

        // ---- one-time lane-pair transpose: thread ends owning 8 rows x 8 d ----
        #pragma unroll
        for (int k = 0; k < 8; k++) {
            unsigned a0 = *(unsigned*)&zr[4 * k];
            unsigned a1 = *(unsigned*)&zr[4 * k + 1];
            unsigned b0 = *(unsigned*)&zr[4 * k + 2];
            unsigned b1 = *(unsigned*)&zr[4 * k + 3];
            unsigned s0 = po ? a0 : b0;
            unsigned s1 = po ? a1 : b1;
            unsigned r0 = __shfl_xor_sync(0xffffffffu, s0, 1);
            unsigned r1 = __shfl_xor_sync(0xffffffffu, s1, 1);
            unsigned o0 = po ? r0 : a0, o1 = po ? r1 : a1;
            unsigned o2 = po ? b0 : r0, o3 = po ? b1 : r1;
            zr[4 * k]     = *(__half2*)&o0;
            zr[4 * k + 1] = *(__half2*)&o1;
            zr[4 * k + 2] = *(__half2*)&o2;
            zr[4 * k + 3] = *(__half2*)&o3;
        }

        // ---- row reciprocal norms ----
        float rzv;
        {
            float sd[8];
            #pragma unroll
            for (int k = 0; k < 8; k++) {
                __half2 h = __hmul2(zr[4 * k], zr[4 * k]);
                h = __hfma2(zr[4 * k + 1], zr[4 * k + 1], h);
                h = __hfma2(zr[4 * k + 2], zr[4 * k + 2], h);
                h = __hfma2(zr[4 * k + 3], zr[4 * k + 3], h);
                float2 fx = __half22float2(h);
                sd[k] = fx.x + fx.y;
            }
            float S = reduce_scatter8(sd, lane);
            rzv = rsqrtf(fmaxf(S, 1e-24f));
        }

        __syncthreads();       // top barrier: us/xs ready; part safe to rewrite

        #pragma unroll
        for (int it = 0; it < 3; it++) {
            // ---- u chunks for the 2 facets (LDS.128, conflict-free) ----
            __half2 uhA[4], uhB[4];
            *(uint4*)uhA = *(const uint4*)uA;
            *(uint4*)uhB = *(const uint4*)uB;

            // ---- 8 row-dots over own 8 d ----
            float dj[8];
            #pragma unroll
            for (int k = 0; k < 8; k++) {
                const __half2* uu = (k & 1) ? uhB : uhA;
                __half2 h = __hmul2(zr[4 * k], uu[0]);
                h = __hfma2(zr[4 * k + 1], uu[1], h);
                h = __hfma2(zr[4 * k + 2], uu[2], h);
                h = __hfma2(zr[4 * k + 3], uu[3], h);
                float2 fx = __half22float2(h);
                dj[k] = fx.x + fx.y;
            }

            // ---- scatter-reduce -> logit; softmax over f ----
            float L = reduce_scatter8(dj, lane) * rzv;
            float e = __expf(L);                    // cosines in [-1,1]
            float s = e;
            s += __shfl_xor_sync(0xffffffffu, s, 1);
            s += __shfl_xor_sync(0xffffffffu, s, 2);
            s += __shfl_xor_sync(0xffffffffu, s, 16);
            float p_eff = __fdividef(e, s) * rzv;

            // ---- packed fp16 gather of own 8 rows' p ----
            __half ph = __float2half(p_eff);
            unsigned pv = (unsigned)__half_as_ushort(ph);
            unsigned p8 = __shfl_xor_sync(0xffffffffu, pv, 8);
            __half2 P2 = __halves2half2(ph, __ushort_as_half((unsigned short)p8));
            unsigned P2u = *(unsigned*)&P2;
            __half2 g[4];
            #pragma unroll
            for (int k = 0; k < 4; k++) {
                unsigned gu = __shfl_sync(0xffffffffu, P2u, gidx | (k << 1));
                g[k] = *(__half2*)&gu;
            }

            // ---- pass 2: fp16 accumulate ----
            __half2 accA[4], accB[4];
            {
                __half2 ph0 = __low2half2(g[0]);
                __half2 ph1 = __low2half2(g[1]);
                #pragma unroll
                for (int r = 0; r < 4; r++) {
                    accA[r] = __hmul2(zr[r], ph0);
                    accB[r] = __hmul2(zr[4 + r], ph1);
                }
                #pragma unroll
                for (int k = 2; k < 8; k++) {
                    __half2 pk = (k < 4) ? __low2half2(g[k]) : __high2half2(g[k - 4]);
                    __half2* acc = (k & 1) ? accB : accA;
                    #pragma unroll
                    for (int r = 0; r < 4; r++)
                        acc[r] = __hfma2(zr[4 * k + r], pk, acc[r]);
                }
            }
            *(uint4*)pA = *(uint4*)accA;
            *(uint4*)pB = *(uint4*)accB;
            __syncthreads();                        // partials visible

            // ---- epilogue: warp f<8 combines 16 partials (fp32), +x ----
            if (w < 8) {
                int d0 = lane * 2;
                float2 v = *(const float2*)(xs + w * XSTR + d0);
                #pragma unroll
                for (int gg = 0; gg < 16; gg++) {
                    __half2 hv = *(const __half2*)(part + gg * PWS + w * PFS + d0);
                    float2 fv = __half22float2(hv);
                    v.x += fv.x; v.y += fv.y;
                }
                if (it < 2) {
                    float s2 = v.x * v.x + v.y * v.y;
                    #pragma unroll
                    for (int o = 16; o; o >>= 1) s2 += __shfl_xor_sync(0xffffffffu, s2, o);
                    float r = rsqrtf(fmaxf(s2, 1e-24f));
                    *(__half2*)(us + w * UH + d0) = __floats2half2_rn(v.x * r, v.y * r);
                } else {
                    __stcs((float2*)(out + (size_t)bi * 512 + w * 64 + d0), v);
                }
            }
            __syncthreads();                        // u ready / end-of-batch fence
        }
    }
}

extern "C" void kernel_launch(void* const* d_in, const int* in_sizes, int n_in,
                              void* d_out, int out_size)
{
    const float* feat = (const float*)d_in[0];   // [B, 512]
    const float* meta = (const float*)d_in[1];   // [B, 64, 512]
    float* out = (float*)d_out;

    const int B = in_sizes[0] / 512;             // 2048
    const size_t smem_bytes = (size_t)SMEM_FLOATS * sizeof(float);

    cudaFuncSetAttribute(hete_attention_kernel,
                         cudaFuncAttributeMaxDynamicSharedMemorySize,
                         (int)smem_bytes);

    hete_attention_kernel<<<GRIDX, NTHREADS, smem_bytes>>>(feat, meta, out, B);
}